// round 2
// baseline (speedup 1.0000x reference)
#include <cuda_runtime.h>
#include <cuda_bf16.h>

// Problem constants
#define NN 4096
#define MM 512
#define DD 32

// Scratch: per-row statistics (no allocations allowed -> device globals)
__device__ float g_R[NN];  // sum_m K[n,m]
__device__ float g_S[NN];  // sum_m K[n,m]*r[n,m]
__device__ float g_T[NN];  // sum_m K[n,m]*C[n,m]*r[n,m]

// ---------------------------------------------------------------------------
// Kernel 1: fused cost/kernel-matrix row statistics.
// One warp per row n; lanes split the m dimension. y staged in SMEM in two
// 256-column halves, layout [m][36 floats] (9 float4 per row) so LDS.128
// reads are bank-conflict-free per phase.
// ---------------------------------------------------------------------------
__global__ __launch_bounds__(256) void rowstats_kernel(
    const float* __restrict__ x,   // [NN, DD]
    const float* __restrict__ y,   // [MM, DD]
    const float* __restrict__ r)   // [NN, MM]
{
    __shared__ float4 ys4[256 * 9];  // half of y: 256 rows x 36 floats (padded)

    const int tid  = threadIdx.x;
    const int warp = tid >> 5;
    const int lane = tid & 31;
    const int n    = blockIdx.x * 8 + warp;

    // Broadcast this row's x into 32 registers (one-time shfl fan-out).
    float xv = x[n * DD + lane];
    float xr[DD];
#pragma unroll
    for (int d = 0; d < DD; d++) xr[d] = __shfl_sync(0xffffffffu, xv, d);

    float Racc = 0.f, Sacc = 0.f, Tacc = 0.f;
    const float*  rrow = r + (size_t)n * MM;
    const float4* y4g  = (const float4*)y;   // y4g[m*8 + k]

    for (int h = 0; h < 2; h++) {
        if (h) __syncthreads();  // previous half fully consumed before overwrite
        // Stage half h of y: 256 rows x 8 float4, padded row stride 9.
        for (int i = tid; i < 2048; i += 256) {
            ys4[(i >> 3) * 9 + (i & 7)] = y4g[h * 2048 + i];
        }
        __syncthreads();

#pragma unroll
        for (int j = 0; j < 8; j++) {
            const int mloc = j * 32 + lane;      // 0..255 within half
            float d2 = 0.f;
#pragma unroll
            for (int k = 0; k < 8; k++) {
                float4 yv = ys4[mloc * 9 + k];
                float t0 = xr[4 * k + 0] - yv.x; d2 = fmaf(t0, t0, d2);
                float t1 = xr[4 * k + 1] - yv.y; d2 = fmaf(t1, t1, d2);
                float t2 = xr[4 * k + 2] - yv.z; d2 = fmaf(t2, t2, d2);
                float t3 = xr[4 * k + 3] - yv.w; d2 = fmaf(t3, t3, d2);
            }
            float C  = sqrtf(d2);
            float K  = __expf(-0.5f * C);        // exp(-C/EPS), EPS=2
            float rv = rrow[h * 256 + mloc];
            Racc += K;
            float Kr = K * rv;
            Sacc += Kr;
            Tacc = fmaf(Kr, C, Tacc);
        }
    }

    // Warp reduction of the three row sums.
#pragma unroll
    for (int off = 16; off > 0; off >>= 1) {
        Racc += __shfl_down_sync(0xffffffffu, Racc, off);
        Sacc += __shfl_down_sync(0xffffffffu, Sacc, off);
        Tacc += __shfl_down_sync(0xffffffffu, Tacc, off);
    }
    if (lane == 0) {
        g_R[n] = Racc;
        g_S[n] = Sacc;
        g_T[n] = Tacc;
    }
}

// ---------------------------------------------------------------------------
// Kernel 2: scalar Sinkhorn recurrence + early stop + output.
// Single block, 1024 threads, 4 rows each (in registers).
//   iter 1:   u = 1/(R + 1e-8)                       (v0 = ones)
//   iter t>1: u = 1/( S/(u_prev+1e-8) + 1e-8 )       (v = r/(u_prev+1e-8))
//   err = mean_n |u_new - u_old|; break when err < 0.1 (after applying update)
//   out[n] = u * T[n] / (u + 1e-8)
// ---------------------------------------------------------------------------
__global__ __launch_bounds__(1024) void sinkhorn_iter_kernel(float* __restrict__ out)
{
    __shared__ float red[32];
    __shared__ float err_sh;

    const int tid  = threadIdx.x;
    const int lane = tid & 31;
    const int warp = tid >> 5;

    float u[4], R[4], S[4], T[4];
#pragma unroll
    for (int k = 0; k < 4; k++) {
        int n = tid + 1024 * k;
        R[k] = g_R[n];
        S[k] = g_S[n];
        T[k] = g_T[n];
        u[k] = 1.0f;
    }

    bool first = true;
    for (int it = 0; it < 100; it++) {
        float local = 0.f;
#pragma unroll
        for (int k = 0; k < 4; k++) {
            float denom = first ? R[k] : (S[k] / (u[k] + 1e-8f));
            float un = 1.0f / (denom + 1e-8f);
            local += fabsf(un - u[k]);
            u[k] = un;
        }
        first = false;

        // Block-wide sum of |u_new - u_old|.
#pragma unroll
        for (int off = 16; off > 0; off >>= 1)
            local += __shfl_down_sync(0xffffffffu, local, off);
        if (lane == 0) red[warp] = local;
        __syncthreads();
        if (warp == 0) {
            float v = red[lane];
#pragma unroll
            for (int off = 16; off > 0; off >>= 1)
                v += __shfl_down_sync(0xffffffffu, v, off);
            if (lane == 0) err_sh = v * (1.0f / (float)NN);
        }
        __syncthreads();
        if (err_sh < 0.1f) break;   // uniform across block
    }

#pragma unroll
    for (int k = 0; k < 4; k++) {
        int n = tid + 1024 * k;
        out[n] = u[k] * T[k] / (u[k] + 1e-8f);
    }
}

extern "C" void kernel_launch(void* const* d_in, const int* in_sizes, int n_in,
                              void* d_out, int out_size)
{
    const float* x = (const float*)d_in[0];  // [4096, 32]
    const float* y = (const float*)d_in[1];  // [512, 32]
    const float* r = (const float*)d_in[2];  // [4096, 512]
    float* out = (float*)d_out;              // [4096]

    rowstats_kernel<<<512, 256>>>(x, y, r);
    sinkhorn_iter_kernel<<<1, 1024>>>(out);
}